// round 3
// baseline (speedup 1.0000x reference)
#include <cuda_runtime.h>

#define T_STEPS 32
#define BB      32
#define NIN     512
#define NH      1024
#define NOUT    256
#define NBLK    148
#define NTHR    512
#define KC      128

// ---------------- device scratch ----------------
__device__ float g_s  [T_STEPS * BB * NH];     // raw s (pre-relu) all steps
__device__ float g_z  [T_STEPS * BB * NH];     // raw z all steps
__device__ float g_zc [T_STEPS * BB * NH];     // zc all steps
__device__ float g_hist[T_STEPS][BB][NH];      // h_new history
__device__ float g_h  [BB * NH];               // normalized carry
__device__ float g_hWP[4][BB * NH];            // h@W_h partials (also o partials)
__device__ float g_hsP[4][BB * NH];            // h_new@W_h partials
__device__ float g_yP [4][BB * NOUT];
__device__ float g_dots[T_STEPS][BB];
__device__ unsigned g_cnt;

// ---------------- f32x2 helpers ----------------
__device__ __forceinline__ unsigned long long pk2(float lo, float hi) {
    unsigned long long r;
    asm("mov.b64 %0, {%1, %2};" : "=l"(r) : "f"(lo), "f"(hi));
    return r;
}
__device__ __forceinline__ void upk2(unsigned long long v, float& lo, float& hi) {
    asm("mov.b64 {%0, %1}, %2;" : "=f"(lo), "=f"(hi) : "l"(v));
}
__device__ __forceinline__ unsigned long long fma2(unsigned long long a,
                                                   unsigned long long b,
                                                   unsigned long long c) {
    unsigned long long d;
    asm("fma.rn.f32x2 %0, %1, %2, %3;" : "=l"(d) : "l"(a), "l"(b), "l"(c));
    return d;
}

// ---------------- grid barrier (wrap-safe monotonic counter) ------------
__device__ __forceinline__ void gsync() {
    __syncthreads();
    if (threadIdx.x == 0) {
        __threadfence();
        unsigned arrival = atomicAdd(&g_cnt, 1u);
        unsigned target  = (arrival / NBLK + 1u) * NBLK;
        while ((int)(*(volatile unsigned*)&g_cnt - target) < 0) { }
        __threadfence();
    }
    __syncthreads();
}

// ---------------- 32-row x 64-col x klen GEMM task ----------------------
// out[r][colbase+c] = sum_k A[r][k] * W[k][c], A = A0(+partials)(+relu).
// 16 warps: colhalf = wg>>3, rowgroup = (wg&7)*4; 4 rows/thread via 2 fma2.
template<int NPART, bool RELU, int KA, int N>
__device__ __forceinline__ void gemm_task(
    float (*As)[BB],
    const float* __restrict__ A0, int rbase,
    const float* __restrict__ P,           // partial base (stride BB*NH)
    const float* __restrict__ W, int k0, int klen,
    float* __restrict__ outp, int colbase)
{
    const int tid  = threadIdx.x;
    const int lane = tid & 31;
    const int wg   = tid >> 5;
    const int ch   = wg >> 3;
    const int rg   = (wg & 7) * 4;
    const int j    = colbase + ch * 32 + lane;
    unsigned long long acc01 = 0ULL, acc23 = 0ULL;

    for (int kb = 0; kb < klen; kb += KC) {
        __syncthreads();
#pragma unroll
        for (int u = 0; u < (KC * BB) / NTHR; ++u) {   // 8
            int idx = u * NTHR + tid;
            int b   = idx & 31;
            int kk  = idx >> 5;
            int gk  = k0 + kb + kk;
            float v = A0[(size_t)(rbase + b) * KA + gk];
#pragma unroll
            for (int c = 0; c < NPART; ++c)
                v += P[(size_t)c * (BB * NH) + b * NH + gk];
            if (RELU) v = fmaxf(v, 0.0f);
            As[kk][b] = v;
        }
        __syncthreads();
        const float* Wp = W + (size_t)(k0 + kb) * N + j;
#pragma unroll 16
        for (int kk = 0; kk < KC; ++kk) {
            float w = Wp[(size_t)kk * N];
            unsigned long long w2 = pk2(w, w);
            ulonglong2 a = *(const ulonglong2*)&As[kk][rg];
            acc01 = fma2(a.x, w2, acc01);
            acc23 = fma2(a.y, w2, acc23);
        }
    }
    float s0, s1, s2, s3;
    upk2(acc01, s0, s1);
    upk2(acc23, s2, s3);
    outp[(rg + 0) * N + j] = s0;
    outp[(rg + 1) * N + j] = s1;
    outp[(rg + 2) * N + j] = s2;
    outp[(rg + 3) * N + j] = s3;
}

// ---------------- persistent kernel ------------------------------------
__global__ void __launch_bounds__(NTHR, 1) memnet_kernel(
    const float* __restrict__ x_in,  const float* __restrict__ W_i,
    const float* __restrict__ W_z,   const float* __restrict__ W_c,
    const float* __restrict__ W_h,   const float* __restrict__ W_ho,
    const float* __restrict__ W_o,   const float* __restrict__ lam_p,
    const float* __restrict__ eta_p, const float* __restrict__ g_p,
    const float* __restrict__ b_p,   float* __restrict__ y_out)
{
    __shared__ float As[KC][BB];        // 16 KB GEMM staging
    __shared__ float hbuf[NH];          // 4 KB (dot CTAs)
    __shared__ float red_s[16][32];
    __shared__ float red_q[16][32];

    const int tid  = threadIdx.x;
    const int bid  = blockIdx.x;
    const int lane = tid & 31;
    const int wg   = tid >> 5;
    const int gtid = bid * NTHR + tid;
    const int gstr = NBLK * NTHR;

    const float lamv = lam_p[0];
    const float etav = eta_p[0];

    // ===== Prologue: hoisted x->s->z->zc (independent of recurrence) =====
    // A: s = relu(x) @ W_i   (M=1024, K=512)   512 tasks
    for (int task = bid; task < 512; task += NBLK) {
        int rb = task >> 4, cc = task & 15;
        gemm_task<0, true, NIN, NH>(As, x_in, rb * 32, 0, W_i, 0, NIN,
                                    g_s + (size_t)rb * 32 * NH, cc * 64);
    }
    gsync();
    // B: z = relu(s) @ W_z   (M=1024, K=1024)
    for (int task = bid; task < 512; task += NBLK) {
        int rb = task >> 4, cc = task & 15;
        gemm_task<0, true, NH, NH>(As, g_s, rb * 32, 0, W_z, 0, NH,
                                   g_z + (size_t)rb * 32 * NH, cc * 64);
    }
    gsync();
    // C: zc = relu(z) @ W_c
    for (int task = bid; task < 512; task += NBLK) {
        int rb = task >> 4, cc = task & 15;
        gemm_task<0, true, NH, NH>(As, g_z, rb * 32, 0, W_c, 0, NH,
                                   g_zc + (size_t)rb * 32 * NH, cc * 64);
    }
    gsync();

    // ===== Recurrent loop =====
    for (int t = 0; t < T_STEPS; ++t) {
        const float* zct = g_zc + (size_t)t * BB * NH;

        // ---- P1: hW partials = h @ W_h (skip at t=0: h==0) ----
        if (t > 0) {
            if (bid < 64) {
                int cc = bid >> 2, ks = bid & 3;
                gemm_task<0, false, NH, NH>(As, g_h, 0, 0, W_h, ks * 256, 256,
                                            g_hWP[ks], cc * 64);
            }
            gsync();
        }

        // ---- P3: hs partials = relu(zc + sum hW) @ W_h  (staging combine)
        //          || dot CTAs: write hist[t][b] + dots[s][b]
        if (bid < 64) {
            int cc = bid >> 2, ks = bid & 3;
            if (t > 0)
                gemm_task<4, true, NH, NH>(As, zct, 0, g_hWP[0], W_h,
                                           ks * 256, 256, g_hsP[ks], cc * 64);
            else
                gemm_task<0, true, NH, NH>(As, zct, 0, 0, W_h,
                                           ks * 256, 256, g_hsP[ks], cc * 64);
        } else if (bid < 96) {
            int b = bid - 64;
            const float* zcb = zct + b * NH;
            for (int i = tid; i < NH; i += NTHR) {
                float v = zcb[i];
                if (t > 0)
                    v += (g_hWP[0][b * NH + i] + g_hWP[1][b * NH + i]) +
                         (g_hWP[2][b * NH + i] + g_hWP[3][b * NH + i]);
                v = fmaxf(v, 0.0f);
                hbuf[i] = v;
                g_hist[t][b][i] = v;
            }
            __syncthreads();
            for (int s = wg; s <= t; s += 16) {
                const float* hs = &g_hist[s][b][0];
                float sum = 0.0f;
#pragma unroll
                for (int jj = lane * 4; jj < NH; jj += 128) {
                    float4 a = *(const float4*)&hbuf[jj];
                    float4 c = *(const float4*)&hs[jj];
                    sum += a.x * c.x + a.y * c.y + a.z * c.z + a.w * c.w;
                }
#pragma unroll
                for (int off = 16; off; off >>= 1)
                    sum += __shfl_xor_sync(0xffffffffu, sum, off);
                if (lane == 0) g_dots[s][b] = sum;
            }
        }
        gsync();

        // ---- P4: hs = hsW + zc + eta * recurrence ; batchnorm ; relu ----
        if (bid < 32) {
            int j = bid * 32 + lane;
            float gv = g_p[j], bv = b_p[j];
            float v[2];
#pragma unroll
            for (int r = 0; r < 2; ++r) {
                int b = wg * 2 + r;
                float base = (g_hsP[0][b * NH + j] + g_hsP[1][b * NH + j]) +
                             (g_hsP[2][b * NH + j] + g_hsP[3][b * NH + j]) +
                             zct[b * NH + j];
                float accr = 0.0f, p = 1.0f;
                for (int s = t; s >= 0; --s) {
                    accr = fmaf(p * g_dots[s][b], g_hist[s][b][j], accr);
                    p *= lamv;
                }
                v[r] = fmaf(etav, accr, base);
            }
            red_s[wg][lane] = v[0] + v[1];
            red_q[wg][lane] = v[0] * v[0] + v[1] * v[1];
            __syncthreads();
            float mu = 0.0f, sq = 0.0f;
#pragma unroll
            for (int w = 0; w < 16; ++w) { mu += red_s[w][lane]; sq += red_q[w][lane]; }
            mu *= (1.0f / BB);
            sq *= (1.0f / BB);
            float sig = sqrtf(fmaxf(sq - mu * mu, 0.0f));
#pragma unroll
            for (int r = 0; r < 2; ++r) {
                float hv = fmaxf(gv * (v[r] - mu) / sig + bv, 0.0f);
                g_h[(wg * 2 + r) * NH + j] = hv;
            }
        }
        gsync();
    }

    // ===== Epilogue =====
    // E1: o partials = h @ W_ho (relu deferred)
    if (bid < 64) {
        int cc = bid >> 2, ks = bid & 3;
        gemm_task<0, false, NH, NH>(As, g_h, 0, 0, W_ho, ks * 256, 256,
                                    g_hWP[ks], cc * 64);
    }
    gsync();
    // E2: y partials = relu(sum oP) @ W_o
    if (bid < 16) {
        int cc = bid >> 2, ks = bid & 3;
        gemm_task<3, true, NH, NOUT>(As, g_hWP[0], 0, g_hWP[1], W_o,
                                     ks * 256, 256, g_yP[ks], cc * 64);
    }
    gsync();
    // E3: y = relu(sum partials)
    for (int i = gtid; i < BB * NOUT; i += gstr) {
        float v = (g_yP[0][i] + g_yP[1][i]) + (g_yP[2][i] + g_yP[3][i]);
        y_out[i] = fmaxf(v, 0.0f);
    }
}

// ---------------- launch ----------------
extern "C" void kernel_launch(void* const* d_in, const int* in_sizes, int n_in,
                              void* d_out, int out_size) {
    (void)in_sizes; (void)n_in; (void)out_size;
    memnet_kernel<<<NBLK, NTHR>>>(
        (const float*)d_in[0],  (const float*)d_in[1], (const float*)d_in[2],
        (const float*)d_in[3],  (const float*)d_in[4], (const float*)d_in[5],
        (const float*)d_in[6],  (const float*)d_in[7], (const float*)d_in[8],
        (const float*)d_in[9],  (const float*)d_in[10], (float*)d_out);
}

// round 4
// speedup vs baseline: 2.4389x; 2.4389x over previous
#include <cuda_runtime.h>

#define T_STEPS 32
#define BB      32
#define NIN     512
#define NH      1024
#define NOUT    256
#define NBLK    148
#define NTHR    512
#define KC      64
#define KS_LOOP 16

// ---------------- device scratch ----------------
__device__ float g_s   [T_STEPS * BB * NH];
__device__ float g_z   [T_STEPS * BB * NH];
__device__ float g_zc  [T_STEPS * BB * NH];
__device__ float g_hist[T_STEPS][BB][NH];
__device__ float g_h   [BB * NH];
__device__ float g_hWP [KS_LOOP][BB * NH];
__device__ float g_hsP [KS_LOOP][BB * NH];
__device__ float g_R   [BB][NH];
__device__ float g_yP  [4][BB * NOUT];
__device__ unsigned g_cnt;

// ---------------- f32x2 helpers ----------------
__device__ __forceinline__ unsigned long long pk2(float lo, float hi) {
    unsigned long long r;
    asm("mov.b64 %0, {%1, %2};" : "=l"(r) : "f"(lo), "f"(hi));
    return r;
}
__device__ __forceinline__ void upk2(unsigned long long v, float& lo, float& hi) {
    asm("mov.b64 {%0, %1}, %2;" : "=f"(lo), "=f"(hi) : "l"(v));
}
__device__ __forceinline__ unsigned long long fma2(unsigned long long a,
                                                   unsigned long long b,
                                                   unsigned long long c) {
    unsigned long long d;
    asm("fma.rn.f32x2 %0, %1, %2, %3;" : "=l"(d) : "l"(a), "l"(b), "l"(c));
    return d;
}

// ---------------- grid barrier (wrap-safe monotonic counter) ------------
__device__ __forceinline__ void gsync() {
    __syncthreads();
    if (threadIdx.x == 0) {
        __threadfence();
        unsigned arrival = atomicAdd(&g_cnt, 1u);
        unsigned target  = (arrival / NBLK + 1u) * NBLK;
        while ((int)(*(volatile unsigned*)&g_cnt - target) < 0) { }
        __threadfence();
    }
    __syncthreads();
}

// ---------------- shared memory union -----------------------------------
struct GemmSh { float As[KC][36]; float Ws[KC][128]; };     // 41 KB
struct MiscSh { float hbuf[NH]; float dbuf[T_STEPS];
                float red_s[16][32]; float red_q[16][32]; };
union Sh { GemmSh g; MiscSh n; };

// ---------------- 32-row x 128-col GEMM task -----------------------------
// out[r][colbase+c] = sum_{k=k0..k0+klen} A[r][k] * W[k][c]
// A optionally combined with NPART extra partial streams (+relu) at staging.
// 16 warps = 4 colq x 4 rg; each thread: 8 rows x 1 col, 4 fma2 chains.
template<int NPART, bool RELU, int KA, int N>
__device__ __forceinline__ void gemm_task(Sh* sh,
    const float* __restrict__ A0, int rbase,
    const float* __restrict__ P,
    const float* __restrict__ W, int k0, int klen,
    float* __restrict__ outp, int colbase)
{
    float (*As)[36]  = sh->g.As;
    float (*Ws)[128] = sh->g.Ws;
    const int tid  = threadIdx.x;
    const int lane = tid & 31;
    const int wg   = tid >> 5;
    const int colq = wg >> 2;
    const int rg   = wg & 3;
    const int tw   = colq * 32 + lane;      // col within 128-wide tile
    const int j    = colbase + tw;

    unsigned long long acc0 = 0, acc1 = 0, acc2 = 0, acc3 = 0;

    for (int kb = 0; kb < klen; kb += KC) {
        __syncthreads();
        // stage A transposed: As[kk][b]
#pragma unroll
        for (int u = 0; u < 4; ++u) {
            int kk = lane + ((u & 1) << 5);
            int b  = wg * 2 + (u >> 1);
            int gk = k0 + kb + kk;
            float v = A0[(size_t)(rbase + b) * KA + gk];
#pragma unroll
            for (int p = 0; p < NPART; ++p)
                v += P[(size_t)p * (BB * NH) + b * NH + gk];
            if (RELU) v = fmaxf(v, 0.0f);
            As[kk][b] = v;
        }
        // stage W: Ws[kk][0..127]
#pragma unroll
        for (int u = 0; u < 4; ++u) {
            int kk = wg * 4 + u;
            int gk = k0 + kb + kk;
            float4 wv = *(const float4*)&W[(size_t)gk * N + colbase + lane * 4];
            *(float4*)&Ws[kk][lane * 4] = wv;
        }
        __syncthreads();
#pragma unroll 16
        for (int kk = 0; kk < KC; ++kk) {
            float w = Ws[kk][tw];
            unsigned long long w2 = pk2(w, w);
            ulonglong2 a01 = *(const ulonglong2*)&As[kk][rg * 8];
            ulonglong2 a23 = *(const ulonglong2*)&As[kk][rg * 8 + 4];
            acc0 = fma2(a01.x, w2, acc0);
            acc1 = fma2(a01.y, w2, acc1);
            acc2 = fma2(a23.x, w2, acc2);
            acc3 = fma2(a23.y, w2, acc3);
        }
    }
    float o[8];
    upk2(acc0, o[0], o[1]);
    upk2(acc1, o[2], o[3]);
    upk2(acc2, o[4], o[5]);
    upk2(acc3, o[6], o[7]);
#pragma unroll
    for (int r = 0; r < 8; ++r)
        outp[(size_t)(rg * 8 + r) * N + j] = o[r];
}

// ---------------- persistent kernel ------------------------------------
__global__ void __launch_bounds__(NTHR, 1) memnet_kernel(
    const float* __restrict__ x_in,  const float* __restrict__ W_i,
    const float* __restrict__ W_z,   const float* __restrict__ W_c,
    const float* __restrict__ W_h,   const float* __restrict__ W_ho,
    const float* __restrict__ W_o,   const float* __restrict__ lam_p,
    const float* __restrict__ eta_p, const float* __restrict__ g_p,
    const float* __restrict__ b_p,   float* __restrict__ y_out)
{
    __shared__ Sh sh;

    const int tid  = threadIdx.x;
    const int bid  = blockIdx.x;
    const int lane = tid & 31;
    const int wg   = tid >> 5;
    const int gtid = bid * NTHR + tid;
    const int gstr = NBLK * NTHR;

    const float lamv = lam_p[0];
    const float etav = eta_p[0];

    // ===== Prologue: hoisted x -> s -> z -> zc (M = 1024 GEMMs) =====
    for (int task = bid; task < 256; task += NBLK) {
        int rb = task >> 3, cb = task & 7;
        gemm_task<0, true, NIN, NH>(&sh, x_in, rb * 32, 0, W_i, 0, NIN,
                                    g_s + (size_t)rb * 32 * NH, cb * 128);
    }
    gsync();
    for (int task = bid; task < 256; task += NBLK) {
        int rb = task >> 3, cb = task & 7;
        gemm_task<0, true, NH, NH>(&sh, g_s, rb * 32, 0, W_z, 0, NH,
                                   g_z + (size_t)rb * 32 * NH, cb * 128);
    }
    gsync();
    for (int task = bid; task < 256; task += NBLK) {
        int rb = task >> 3, cb = task & 7;
        gemm_task<0, true, NH, NH>(&sh, g_z, rb * 32, 0, W_c, 0, NH,
                                   g_zc + (size_t)rb * 32 * NH, cb * 128);
    }
    gsync();

    // ===== Recurrent loop =====
    for (int t = 0; t < T_STEPS; ++t) {
        const float* zct = g_zc + (size_t)t * BB * NH;

        // ---- P1: hW partials = h @ W_h  (skip t=0: h == 0) ----
        if (t > 0) {
            if (bid < 128) {
                int cb = bid >> 4, ks = bid & 15;
                gemm_task<0, false, NH, NH>(&sh, g_h, 0, 0, W_h, ks * 64, 64,
                                            g_hWP[ks], cb * 128);
            }
            gsync();
        }

        // ---- C: combine -> hist[t], dots, lambda-scan readout R ----
        if (bid < BB) {
            int b = bid;
            int j0 = tid * 2;
            // combine + relu
            float v0 = zct[b * NH + j0], v1 = zct[b * NH + j0 + 1];
            if (t > 0) {
#pragma unroll
                for (int p = 0; p < KS_LOOP; ++p) {
                    v0 += g_hWP[p][b * NH + j0];
                    v1 += g_hWP[p][b * NH + j0 + 1];
                }
            }
            v0 = fmaxf(v0, 0.0f);
            v1 = fmaxf(v1, 0.0f);
            sh.n.hbuf[j0] = v0;
            sh.n.hbuf[j0 + 1] = v1;
            g_hist[t][b][j0]     = v0;
            g_hist[t][b][j0 + 1] = v1;
            __syncthreads();
            // dots[s] = h_t . h_s
            for (int s = wg; s <= t; s += 16) {
                const float* hs = &g_hist[s][b][0];
                float sum = 0.0f;
#pragma unroll
                for (int jj = lane * 4; jj < NH; jj += 128) {
                    float4 a = *(const float4*)&sh.n.hbuf[jj];
                    float4 c = *(const float4*)&hs[jj];
                    sum += a.x * c.x + a.y * c.y + a.z * c.z + a.w * c.w;
                }
#pragma unroll
                for (int off = 16; off; off >>= 1)
                    sum += __shfl_xor_sync(0xffffffffu, sum, off);
                if (lane == 0) sh.n.dbuf[s] = sum;
            }
            __syncthreads();
            if (tid == 0) {       // w[s] = eta * lam^(t-s) * dot
                float p = etav;
                for (int s = t; s >= 0; --s) { sh.n.dbuf[s] *= p; p *= lamv; }
            }
            __syncthreads();
            // R[b][j] = sum_s w[s] * hist[s][b][j]
            float a0 = 0.0f, a1 = 0.0f;
            for (int s = 0; s <= t; ++s) {
                float ws = sh.n.dbuf[s];
                float2 hv = *(const float2*)&g_hist[s][b][j0];
                a0 = fmaf(ws, hv.x, a0);
                a1 = fmaf(ws, hv.y, a1);
            }
            g_R[b][j0]     = a0;
            g_R[b][j0 + 1] = a1;
        }
        gsync();

        // ---- P3: hs partials = hist[t] @ W_h ----
        if (bid < 128) {
            int cb = bid >> 4, ks = bid & 15;
            gemm_task<0, false, NH, NH>(&sh, &g_hist[t][0][0], 0, 0, W_h,
                                        ks * 64, 64, g_hsP[ks], cb * 128);
        }
        gsync();

        // ---- N: hs = sum hsP + zc + R ; batchnorm ; relu ----
        if (bid < 32) {
            int j = bid * 32 + lane;
            float gv = g_p[j], bv = b_p[j];
            float v[2];
#pragma unroll
            for (int r = 0; r < 2; ++r) {
                int b = wg * 2 + r;
                float base = zct[b * NH + j] + g_R[b][j];
#pragma unroll
                for (int p = 0; p < KS_LOOP; ++p)
                    base += g_hsP[p][b * NH + j];
                v[r] = base;
            }
            sh.n.red_s[wg][lane] = v[0] + v[1];
            sh.n.red_q[wg][lane] = v[0] * v[0] + v[1] * v[1];
            __syncthreads();
            float mu = 0.0f, sq = 0.0f;
#pragma unroll
            for (int w = 0; w < 16; ++w) {
                mu += sh.n.red_s[w][lane];
                sq += sh.n.red_q[w][lane];
            }
            mu *= (1.0f / BB);
            sq *= (1.0f / BB);
            float sig = sqrtf(fmaxf(sq - mu * mu, 0.0f));
#pragma unroll
            for (int r = 0; r < 2; ++r) {
                float hv = fmaxf(gv * (v[r] - mu) / sig + bv, 0.0f);
                g_h[(wg * 2 + r) * NH + j] = hv;
            }
        }
        gsync();
    }

    // ===== Epilogue =====
    // E1: o partials = h @ W_ho  (raw; relu at E2 staging) -> reuse hWP[0..3]
    if (bid < 32) {
        int cb = bid >> 2, ks = bid & 3;
        gemm_task<0, false, NH, NH>(&sh, g_h, 0, 0, W_ho, ks * 256, 256,
                                    g_hWP[ks], cb * 128);
    }
    gsync();
    // E2: y partials = relu(sum oP) @ W_o
    if (bid < 8) {
        int cb = bid >> 2, ks = bid & 3;
        gemm_task<3, true, NH, NOUT>(&sh, g_hWP[0], 0, g_hWP[1], W_o,
                                     ks * 256, 256,
                                     g_yP[ks], cb * 128);
    }
    gsync();
    // E3: y = relu(sum partials)
    for (int i = gtid; i < BB * NOUT; i += gstr) {
        float v = (g_yP[0][i] + g_yP[1][i]) + (g_yP[2][i] + g_yP[3][i]);
        y_out[i] = fmaxf(v, 0.0f);
    }
}

// ---------------- launch ----------------
extern "C" void kernel_launch(void* const* d_in, const int* in_sizes, int n_in,
                              void* d_out, int out_size) {
    (void)in_sizes; (void)n_in; (void)out_size;
    memnet_kernel<<<NBLK, NTHR>>>(
        (const float*)d_in[0],  (const float*)d_in[1], (const float*)d_in[2],
        (const float*)d_in[3],  (const float*)d_in[4], (const float*)d_in[5],
        (const float*)d_in[6],  (const float*)d_in[7], (const float*)d_in[8],
        (const float*)d_in[9],  (const float*)d_in[10], (float*)d_out);
}

// round 6
// speedup vs baseline: 2.6677x; 1.0938x over previous
#include <cuda_runtime.h>

#define T_STEPS 32
#define BB      32
#define NIN     512
#define NH      1024
#define NOUT    256
#define NBLK    148
#define NTHR    512
#define KC      64
#define KS_LOOP 16

// ---------------- device scratch ----------------
__device__ float g_s   [T_STEPS * BB * NH];     // relu'ed s
__device__ float g_z   [T_STEPS * BB * NH];     // relu'ed z
__device__ float g_zc  [T_STEPS * BB * NH];     // raw zc
__device__ float g_hist[T_STEPS][BB][NH];
__device__ float g_h   [BB * NH];
__device__ float g_hWP [KS_LOOP][BB * NH];
__device__ float g_hsP [KS_LOOP][BB * NH];
__device__ float g_R   [BB][NH];
__device__ float g_yP  [4][BB * NOUT];
__device__ unsigned g_cnt;

// ---------------- f32x2 helpers ----------------
__device__ __forceinline__ unsigned long long pk2(float lo, float hi) {
    unsigned long long r;
    asm("mov.b64 %0, {%1, %2};" : "=l"(r) : "f"(lo), "f"(hi));
    return r;
}
__device__ __forceinline__ void upk2(unsigned long long v, float& lo, float& hi) {
    asm("mov.b64 {%0, %1}, %2;" : "=f"(lo), "=f"(hi) : "l"(v));
}
__device__ __forceinline__ unsigned long long fma2(unsigned long long a,
                                                   unsigned long long b,
                                                   unsigned long long c) {
    unsigned long long d;
    asm("fma.rn.f32x2 %0, %1, %2, %3;" : "=l"(d) : "l"(a), "l"(b), "l"(c));
    return d;
}

// ---------------- grid barrier ----------------
__device__ __forceinline__ void gsync() {
    __syncthreads();
    if (threadIdx.x == 0) {
        __threadfence();
        unsigned arrival = atomicAdd(&g_cnt, 1u);
        unsigned target  = (arrival / NBLK + 1u) * NBLK;
        while ((int)(*(volatile unsigned*)&g_cnt - target) < 0) { }
        __threadfence();
    }
    __syncthreads();
}

// ---------------- shared memory ----------------
struct ProSh { float As[KC][36]; float Ws[KC][128]; };          // 41 KB
struct LoopSh {
    float Wh[KC][128];                                          // persistent W_h tile
    float As[KC][36];
    union {
        struct { float hbuf[NH]; float dbuf[T_STEPS]; } c;
        struct { float red_s[16][32]; float red_q[16][32]; } n;
    } m;
};                                                              // 45.2 KB

// ---------------- shared inner compute (64 kk) --------------------------
__device__ __forceinline__ void compute64(const float (*As)[36],
                                          const float (*Ws)[128],
                                          int rg, int tw,
                                          unsigned long long& a0, unsigned long long& a1,
                                          unsigned long long& a2, unsigned long long& a3)
{
#pragma unroll 16
    for (int kk = 0; kk < KC; ++kk) {
        float w = Ws[kk][tw];
        unsigned long long w2 = pk2(w, w);
        ulonglong2 p01 = *(const ulonglong2*)&As[kk][rg * 8];
        ulonglong2 p23 = *(const ulonglong2*)&As[kk][rg * 8 + 4];
        a0 = fma2(p01.x, w2, a0);
        a1 = fma2(p01.y, w2, a1);
        a2 = fma2(p23.x, w2, a2);
        a3 = fma2(p23.y, w2, a3);
    }
}

// ---------------- multi-block GEMM (prologue/epilogue) ------------------
// out[32r x 128c] = A[32 x klen] @ W[klen x 128c]; reg double-buffered.
template<int NPART, bool RELU_IN, bool RELU_OUT, int KA, int N>
__device__ __forceinline__ void gemm_pro(ProSh* sh,
    const float* __restrict__ A0, int rbase,
    const float* __restrict__ P,
    const float* __restrict__ W, int k0, int klen,
    float* __restrict__ outp, int colbase)
{
    const int tid  = threadIdx.x;
    const int lane = tid & 31;
    const int wg   = tid >> 5;
    const int colq = wg >> 2;
    const int rg   = wg & 3;
    const int tw   = colq * 32 + lane;
    const int j    = colbase + tw;

    unsigned long long a0 = 0, a1 = 0, a2 = 0, a3 = 0;
    float  av[4];
    float4 wr[4];

    // prefetch block 0
#pragma unroll
    for (int u = 0; u < 4; ++u) {
        int kk = lane + ((u & 1) << 5);
        int b  = wg * 2 + (u >> 1);
        int gk = k0 + kk;
        float v = A0[(size_t)(rbase + b) * KA + gk];
#pragma unroll
        for (int p = 0; p < NPART; ++p)
            v += P[(size_t)p * (BB * NH) + b * NH + gk];
        if (RELU_IN) v = fmaxf(v, 0.0f);
        av[u] = v;
    }
#pragma unroll
    for (int u = 0; u < 4; ++u)
        wr[u] = *(const float4*)&W[(size_t)(k0 + wg * 4 + u) * N + colbase + lane * 4];

    for (int kb = 0; kb < klen; kb += KC) {
        __syncthreads();
#pragma unroll
        for (int u = 0; u < 4; ++u) {
            int kk = lane + ((u & 1) << 5);
            int b  = wg * 2 + (u >> 1);
            sh->As[kk][b] = av[u];
        }
#pragma unroll
        for (int u = 0; u < 4; ++u)
            *(float4*)&sh->Ws[wg * 4 + u][lane * 4] = wr[u];
        __syncthreads();
        if (kb + KC < klen) {     // prefetch next block (overlaps compute)
            int kn = k0 + kb + KC;
#pragma unroll
            for (int u = 0; u < 4; ++u) {
                int kk = lane + ((u & 1) << 5);
                int b  = wg * 2 + (u >> 1);
                int gk = kn + kk;
                float v = A0[(size_t)(rbase + b) * KA + gk];
#pragma unroll
                for (int p = 0; p < NPART; ++p)
                    v += P[(size_t)p * (BB * NH) + b * NH + gk];
                if (RELU_IN) v = fmaxf(v, 0.0f);
                av[u] = v;
            }
#pragma unroll
            for (int u = 0; u < 4; ++u)
                wr[u] = *(const float4*)&W[(size_t)(kn + wg * 4 + u) * N + colbase + lane * 4];
        }
        compute64(sh->As, sh->Ws, rg, tw, a0, a1, a2, a3);
    }
    float o[8];
    upk2(a0, o[0], o[1]); upk2(a1, o[2], o[3]);
    upk2(a2, o[4], o[5]); upk2(a3, o[6], o[7]);
#pragma unroll
    for (int r = 0; r < 8; ++r) {
        float v = o[r];
        if (RELU_OUT) v = fmaxf(v, 0.0f);
        outp[(size_t)(rg * 8 + r) * N + j] = v;
    }
}

// ---------------- loop GEMM: persistent Wh, A-staging only --------------
__device__ __forceinline__ void gemm_loop(LoopSh* sh,
    const float* __restrict__ A0, int k0,
    float* __restrict__ outp, int colbase)
{
    const int tid  = threadIdx.x;
    const int lane = tid & 31;
    const int wg   = tid >> 5;
    const int colq = wg >> 2;
    const int rg   = wg & 3;
    const int tw   = colq * 32 + lane;
    const int j    = colbase + tw;

    unsigned long long a0 = 0, a1 = 0, a2 = 0, a3 = 0;
#pragma unroll
    for (int u = 0; u < 4; ++u) {
        int kk = lane + ((u & 1) << 5);
        int b  = wg * 2 + (u >> 1);
        sh->As[kk][b] = A0[(size_t)b * NH + k0 + kk];
    }
    __syncthreads();
    compute64(sh->As, sh->Wh, rg, tw, a0, a1, a2, a3);
    float o[8];
    upk2(a0, o[0], o[1]); upk2(a1, o[2], o[3]);
    upk2(a2, o[4], o[5]); upk2(a3, o[6], o[7]);
#pragma unroll
    for (int r = 0; r < 8; ++r)
        outp[(size_t)(rg * 8 + r) * NH + j] = o[r];
}

// ---------------- persistent kernel ------------------------------------
__global__ void __launch_bounds__(NTHR, 1) memnet_kernel(
    const float* __restrict__ x_in,  const float* __restrict__ W_i,
    const float* __restrict__ W_z,   const float* __restrict__ W_c,
    const float* __restrict__ W_h,   const float* __restrict__ W_ho,
    const float* __restrict__ W_o,   const float* __restrict__ lam_p,
    const float* __restrict__ eta_p, const float* __restrict__ g_p,
    const float* __restrict__ b_p,   float* __restrict__ y_out)
{
    extern __shared__ char dsm[];
    ProSh*  psh = (ProSh*)dsm;
    LoopSh* lsh = (LoopSh*)dsm;

    const int tid  = threadIdx.x;
    const int bid  = blockIdx.x;
    const int lane = tid & 31;
    const int wg   = tid >> 5;
    const int gtid = bid * NTHR + tid;
    const int gstr = NBLK * NTHR;

    const float lamv = lam_p[0];
    const float etav = eta_p[0];

    // ===== Prologue: hoisted x -> s -> z -> zc =====
    for (int task = bid; task < 256; task += NBLK) {
        int rb = task >> 3, cb = task & 7;
        gemm_pro<0, true, true, NIN, NH>(psh, x_in, rb * 32, 0, W_i, 0, NIN,
                                         g_s + (size_t)rb * 32 * NH, cb * 128);
    }
    gsync();
    for (int task = bid; task < 256; task += NBLK) {
        int rb = task >> 3, cb = task & 7;
        gemm_pro<0, false, true, NH, NH>(psh, g_s, rb * 32, 0, W_z, 0, NH,
                                         g_z + (size_t)rb * 32 * NH, cb * 128);
    }
    gsync();
    for (int task = bid; task < 256; task += NBLK) {
        int rb = task >> 3, cb = task & 7;
        gemm_pro<0, false, false, NH, NH>(psh, g_z, rb * 32, 0, W_c, 0, NH,
                                          g_zc + (size_t)rb * 32 * NH, cb * 128);
    }
    // load persistent W_h tile (own tile; no cross-CTA dep)
    if (bid < 128) {
        int cb = bid >> 4, ks = bid & 15;
#pragma unroll
        for (int u = 0; u < 4; ++u) {
            int kk = wg * 4 + u;
            *(float4*)&lsh->Wh[kk][lane * 4] =
                *(const float4*)&W_h[(size_t)(ks * 64 + kk) * NH + cb * 128 + lane * 4];
        }
    }
    gsync();

    // ===== Recurrent loop =====
    for (int t = 0; t < T_STEPS; ++t) {
        const float* zct = g_zc + (size_t)t * BB * NH;

        // ---- P1: hW partials = h @ W_h (skip t=0) ----
        if (t > 0) {
            if (bid < 128) {
                int cb = bid >> 4, ks = bid & 15;
                gemm_loop(lsh, g_h, ks * 64, g_hWP[ks], cb * 128);
            }
            gsync();
        }

        // ---- C: combine -> hist[t], dots, lambda-scan readout R ----
        if (bid < BB) {
            int b = bid;
            int j0 = tid * 2;
            float v0 = zct[b * NH + j0], v1 = zct[b * NH + j0 + 1];
            if (t > 0) {
#pragma unroll
                for (int p = 0; p < KS_LOOP; ++p) {
                    v0 += g_hWP[p][b * NH + j0];
                    v1 += g_hWP[p][b * NH + j0 + 1];
                }
            }
            v0 = fmaxf(v0, 0.0f);
            v1 = fmaxf(v1, 0.0f);
            lsh->m.c.hbuf[j0]     = v0;
            lsh->m.c.hbuf[j0 + 1] = v1;
            g_hist[t][b][j0]     = v0;
            g_hist[t][b][j0 + 1] = v1;
            __syncthreads();
            for (int s = wg; s <= t; s += 16) {
                const float* hs = &g_hist[s][b][0];
                float sum = 0.0f;
#pragma unroll
                for (int jj = lane * 4; jj < NH; jj += 128) {
                    float4 a = *(const float4*)&lsh->m.c.hbuf[jj];
                    float4 c = *(const float4*)&hs[jj];
                    sum += a.x * c.x + a.y * c.y + a.z * c.z + a.w * c.w;
                }
#pragma unroll
                for (int off = 16; off; off >>= 1)
                    sum += __shfl_xor_sync(0xffffffffu, sum, off);
                if (lane == 0) lsh->m.c.dbuf[s] = sum;
            }
            __syncthreads();
            if (tid == 0) {
                float p = etav;
                for (int s = t; s >= 0; --s) { lsh->m.c.dbuf[s] *= p; p *= lamv; }
            }
            __syncthreads();
            float a0 = 0.0f, a1 = 0.0f;
            for (int s = 0; s <= t; ++s) {
                float ws = lsh->m.c.dbuf[s];
                float2 hv = *(const float2*)&g_hist[s][b][j0];
                a0 = fmaf(ws, hv.x, a0);
                a1 = fmaf(ws, hv.y, a1);
            }
            g_R[b][j0]     = a0;
            g_R[b][j0 + 1] = a1;
        }
        gsync();

        // ---- P3: hs partials = hist[t] @ W_h ----
        if (bid < 128) {
            int cb = bid >> 4, ks = bid & 15;
            gemm_loop(lsh, &g_hist[t][0][0], ks * 64, g_hsP[ks], cb * 128);
        }
        gsync();

        // ---- N: hs = sum hsP + zc + R ; batchnorm ; relu ----
        if (bid < 32) {
            int j = bid * 32 + lane;
            float gv = g_p[j], bv = b_p[j];
            float v[2];
#pragma unroll
            for (int r = 0; r < 2; ++r) {
                int b = wg * 2 + r;
                float base = zct[b * NH + j] + g_R[b][j];
#pragma unroll
                for (int p = 0; p < KS_LOOP; ++p)
                    base += g_hsP[p][b * NH + j];
                v[r] = base;
            }
            lsh->m.n.red_s[wg][lane] = v[0] + v[1];
            lsh->m.n.red_q[wg][lane] = v[0] * v[0] + v[1] * v[1];
            __syncthreads();
            float mu = 0.0f, sq = 0.0f;
#pragma unroll
            for (int w = 0; w < 16; ++w) {
                mu += lsh->m.n.red_s[w][lane];
                sq += lsh->m.n.red_q[w][lane];
            }
            mu *= (1.0f / BB);
            sq *= (1.0f / BB);
            float sig = sqrtf(fmaxf(sq - mu * mu, 0.0f));
#pragma unroll
            for (int r = 0; r < 2; ++r) {
                float hv = fmaxf(gv * (v[r] - mu) / sig + bv, 0.0f);
                g_h[(wg * 2 + r) * NH + j] = hv;
            }
        }
        gsync();
    }

    // ===== Epilogue =====
    // E1: o partials = h @ W_ho  (128 tasks, 16-way K split)
    if (bid < 128) {
        int cb = bid >> 4, ks = bid & 15;
        gemm_pro<0, false, false, NH, NH>(psh, g_h, 0, 0, W_ho, ks * 64, 64,
                                          g_hWP[ks], cb * 128);
    }
    gsync();
    // E2: y partials = relu(sum oP) @ W_o  (8 tasks)
    if (bid < 8) {
        int cb = bid >> 2, ks = bid & 3;
        gemm_pro<15, true, false, NH, NOUT>(psh, g_hWP[0], 0, g_hWP[1], W_o,
                                            ks * 256, 256, g_yP[ks], cb * 128);
    }
    gsync();
    // E3: y = relu(sum partials)
    for (int i = gtid; i < BB * NOUT; i += gstr) {
        float v = (g_yP[0][i] + g_yP[1][i]) + (g_yP[2][i] + g_yP[3][i]);
        y_out[i] = fmaxf(v, 0.0f);
    }
}

// ---------------- launch ----------------
extern "C" void kernel_launch(void* const* d_in, const int* in_sizes, int n_in,
                              void* d_out, int out_size) {
    (void)in_sizes; (void)n_in; (void)out_size;
    size_t dyn = sizeof(LoopSh) > sizeof(ProSh) ? sizeof(LoopSh) : sizeof(ProSh);
    memnet_kernel<<<NBLK, NTHR, dyn>>>(
        (const float*)d_in[0],  (const float*)d_in[1], (const float*)d_in[2],
        (const float*)d_in[3],  (const float*)d_in[4], (const float*)d_in[5],
        (const float*)d_in[6],  (const float*)d_in[7], (const float*)d_in[8],
        (const float*)d_in[9],  (const float*)d_in[10], (float*)d_out);
}